// round 14
// baseline (speedup 1.0000x reference)
#include <cuda_runtime.h>
#include <cuda_fp16.h>

#define NN 100000
#define EE 1600000
#define HD 64
#define NB 391            // ceil(NN/256)

typedef unsigned long long ull;
typedef unsigned int u32;

// Scratch (device globals: no allocation allowed)
__device__ int    g_degi[NN];
__device__ int    g_off[NN + 1];
__device__ int    g_part[NB];
__device__ int    g_rank[EE];       // edge's arrival rank within its dst
__device__ int    g_esrc[EE];
__device__ float  g_h[NN * HD];
__device__ __half g_hs[NN * HD];    // h * dinv   (fp16: non-negative summands)
__device__ float  g_agg[NN * HD];   // segsum(hs)
__device__ __half g_aggs[NN * HD];  // agg * dinv^2 (fp16)
__device__ float  g_B[NN * HD];     // segsum(aggs)

// Pre-split weight fragments: uint4{bh0,bh1,bl0,bl1} per (kt, ntile, lane)
__device__ uint4  g_w1f[8 * 8 * 32];    // W1  [64][128]: 8 kt x 8 nt
__device__ uint4  g_w2f[4 * 8 * 32];    // W2  [64][64]:  4 kt x 8 nt
__device__ uint4  g_cw1f[4 * 8 * 32];   // cW1 [64][64] (unused after M-fusion; kept in prep)
__device__ uint4  g_w3f[12 * 8 * 32];   // W3  [64][192]: 12 kt x 8 nt
__device__ uint4  g_mf[4 * 8 * 32];     // M = 3*W3[:,0:64]@cW1 [64][64]

// ---------------------------------------------------------------------------
__device__ __forceinline__ void mma16816(float* c, u32 a0, u32 a1, u32 a2, u32 a3,
                                         u32 b0, u32 b1) {
    asm volatile(
        "mma.sync.aligned.m16n8k16.row.col.f32.f16.f16.f32 "
        "{%0,%1,%2,%3}, {%4,%5,%6,%7}, {%8,%9}, {%0,%1,%2,%3};"
        : "+f"(c[0]), "+f"(c[1]), "+f"(c[2]), "+f"(c[3])
        : "r"(a0), "r"(a1), "r"(a2), "r"(a3), "r"(b0), "r"(b1));
}

// 3-term split-fp16 MMA: C += Ah*Bh + Al*Bh + Ah*Bl
__device__ __forceinline__ void mma3(float* c,
                                     u32 ah0, u32 ah1, u32 ah2, u32 ah3,
                                     u32 al0, u32 al1, u32 al2, u32 al3,
                                     uint4 b) {
    mma16816(c, ah0, ah1, ah2, ah3, b.x, b.y);
    mma16816(c, al0, al1, al2, al3, b.x, b.y);
    mma16816(c, ah0, ah1, ah2, ah3, b.z, b.w);
}

__device__ __forceinline__ void st4split(__half* ph, __half* pl, float4 v) {
    __half2 h0 = __floats2half2_rn(v.x, v.y);
    float2 f0 = __half22float2(h0);
    __half2 l0 = __floats2half2_rn(v.x - f0.x, v.y - f0.y);
    __half2 h1 = __floats2half2_rn(v.z, v.w);
    float2 f1 = __half22float2(h1);
    __half2 l1 = __floats2half2_rn(v.z - f1.x, v.w - f1.y);
    *(__half2*)ph = h0; *(__half2*)(ph + 2) = h1;
    *(__half2*)pl = l0; *(__half2*)(pl + 2) = l1;
}

__device__ __forceinline__ void st2split(__half* ph, __half* pl, float x, float y) {
    __half2 h = __floats2half2_rn(x, y);
    float2 f = __half22float2(h);
    *(__half2*)ph = h;
    *(__half2*)pl = __floats2half2_rn(x - f.x, y - f.y);
}

__device__ __forceinline__ uint4 split_frag(float w0, float w1, float w8, float w9) {
    __half2 h0 = __floats2half2_rn(w0, w1);
    float2 f0 = __half22float2(h0);
    __half2 l0 = __floats2half2_rn(w0 - f0.x, w1 - f0.y);
    __half2 h1 = __floats2half2_rn(w8, w9);
    float2 f1 = __half22float2(h1);
    __half2 l1 = __floats2half2_rn(w8 - f1.x, w9 - f1.y);
    uint4 v;
    v.x = *(u32*)&h0; v.y = *(u32*)&h1; v.z = *(u32*)&l0; v.w = *(u32*)&l1;
    return v;
}

__device__ __forceinline__ float dinv_of(int n) {
    return rsqrtf(fmaxf((float)g_degi[n], 1.0f));
}

// ---------------------------------------------------------------------------
// Fused prep: weight pre-split (first 7168 threads) + degree zeroing (all)
__global__ void prep_kernel(const float* __restrict__ W1, const float* __restrict__ W2,
                            const float* __restrict__ cW1, const float* __restrict__ W3) {
    int i = blockIdx.x * 256 + threadIdx.x;
    if (i < NN) g_degi[i] = 0;
    if (i >= 224 * 32) return;
    int gfrag = i >> 5, lane = i & 31;
    const float* W; uint4* out; int K; int g;
    if (gfrag < 64)       { W = W1;  out = g_w1f;  K = 128; g = gfrag; }
    else if (gfrag < 96)  { W = W2;  out = g_w2f;  K = 64;  g = gfrag - 64; }
    else if (gfrag < 128) { W = cW1; out = g_cw1f; K = 64;  g = gfrag - 96; }
    else                  { W = W3;  out = g_w3f;  K = 192; g = gfrag - 128; }
    int kt = g >> 3, nt = g & 7;
    int n = nt * 8 + (lane >> 2), k = kt * 16 + (lane & 3) * 2;
    const float* p = W + n * K + k;
    out[g * 32 + lane] = split_frag(p[0], p[1], p[8], p[9]);
}

// Fused weight M = 3 * W3[:,0:64] @ cW1  ->  fragments (single block)
__global__ void mfuse_kernel(const float* __restrict__ cW1, const float* __restrict__ W3) {
    __shared__ float sC[64 * 64];   // cW1[c][k]
    __shared__ float sW[64 * 64];   // W3[n][c], c < 64
    int t = threadIdx.x;
    for (int i = t; i < 4096; i += 256) sC[i] = cW1[i];
    for (int i = t; i < 4096; i += 256) {
        int n = i >> 6, c = i & 63;
        sW[i] = W3[n * 192 + c];
    }
    __syncthreads();
    int n = t >> 2, ks = (t & 3) * 16;
    float m[16];
#pragma unroll
    for (int q = 0; q < 16; q++) m[q] = 0.f;
    for (int c = 0; c < 64; c++) {
        float w = sW[n * 64 + c];
        const float* cr = sC + c * 64 + ks;
#pragma unroll
        for (int q = 0; q < 16; q++) m[q] += w * cr[q];
    }
    __syncthreads();   // done reading sC; reuse as M storage
#pragma unroll
    for (int q = 0; q < 16; q++) sC[n * 64 + ks + q] = 3.f * m[q];
    __syncthreads();
    for (int idx = t; idx < 1024; idx += 256) {
        int g = idx >> 5, lane = idx & 31;
        int kt = g >> 3, nt = g & 7;
        int nn = nt * 8 + (lane >> 2), kk = kt * 16 + (lane & 3) * 2;
        const float* p = sC + nn * 64 + kk;
        g_mf[g * 32 + lane] = split_frag(p[0], p[1], p[8], p[9]);
    }
}

// ---------------------------------------------------------------------------
// Degrees + per-edge arrival rank (rank reused by csr_fill -> no atomics there)
__global__ void degi_kernel(const int* __restrict__ dst) {
    int e = blockIdx.x * 256 + threadIdx.x;
    if (e < EE) g_rank[e] = atomicAdd(&g_degi[dst[e]], 1);
}

__global__ void scan1_kernel() {
    __shared__ int s[256];
    int t = threadIdx.x;
    int i = blockIdx.x * 256 + t;
    int v = (i < NN) ? g_degi[i] : 0;
    s[t] = v;
    __syncthreads();
#pragma unroll
    for (int d = 1; d < 256; d <<= 1) {
        int tv = (t >= d) ? s[t - d] : 0;
        __syncthreads();
        s[t] += tv;
        __syncthreads();
    }
    if (i < NN) g_off[i] = s[t] - v;
    if (t == 255) g_part[blockIdx.x] = s[255];
}

__global__ void scan23_kernel() {
    __shared__ int ssum[256];
    int t = threadIdx.x, bid = blockIdx.x;
    int v = 0;
    for (int i = t; i < bid; i += 256) v += g_part[i];
    ssum[t] = v;
    __syncthreads();
#pragma unroll
    for (int d = 128; d > 0; d >>= 1) {
        if (t < d) ssum[t] += ssum[t + d];
        __syncthreads();
    }
    int prefix = ssum[0];
    int i = bid * 256 + t;
    if (i < NN) g_off[i] += prefix;
    if (i == 0) g_off[NN] = EE;
}

__global__ void csr_fill_kernel(const int* __restrict__ src, const int* __restrict__ dst) {
    int e = blockIdx.x * 256 + threadIdx.x;
    if (e < EE) {
        int d = dst[e];
        g_esrc[g_off[d] + g_rank[e]] = src[e];
    }
}

// Coalesced hs = fp16(h * dinv). Decouples mlp from degi on the DAG.
__global__ void scale_kernel() {
    int i = blockIdx.x * 256 + threadIdx.x;
    if (i < NN * 32) {
        int n = i >> 5;
        float di = dinv_of(n);
        float2 h = ((const float2*)g_h)[i];
        ((__half2*)g_hs)[i] = __floats2half2_rn(h.x * di, h.y * di);
    }
}

// ---------------------------------------------------------------------------
// Fused 2-layer MLP, split-fp16 tensor cores; weights from pre-split frags.
#define M_AH   0                 // half [64][136]  17408
#define M_AL   17408
#define M_TH   0                 // aliases AH after L1
#define M_TL   9216
#define M_B1   34816
#define M_B2   35072
#define MLP_SMEM_BYTES 35328

__global__ __launch_bounds__(256) void mlp_kernel(
    const float* __restrict__ X, const float* __restrict__ b1,
    const float* __restrict__ b2)
{
    extern __shared__ char smc[];
    __half* sAh = (__half*)(smc + M_AH);
    __half* sAl = (__half*)(smc + M_AL);
    __half* sTh = (__half*)(smc + M_TH);
    __half* sTl = (__half*)(smc + M_TL);
    float*  sB1 = (float*)(smc + M_B1);
    float*  sB2 = (float*)(smc + M_B2);

    int tid = threadIdx.x;
    int base = blockIdx.x * 64;

    for (int i = tid; i < 2048; i += 256) {
        int row = i >> 5, q = i & 31;
        float4 v = make_float4(0.f, 0.f, 0.f, 0.f);
        if (base + row < NN) v = *(const float4*)(X + (size_t)(base + row) * 128 + q * 4);
        st4split(sAh + row * 136 + q * 4, sAl + row * 136 + q * 4, v);
    }
    if (tid < 64) { sB1[tid] = b1[tid]; sB2[tid] = b2[tid]; }
    __syncthreads();

    int wid = tid >> 5, lane = tid & 31;
    int g = lane >> 2, t2 = (lane & 3) * 2;
    int m0 = (wid & 3) * 16, n0 = (wid >> 2) * 32;
    int ntb = (wid >> 2) * 4;

    float acc[4][4];
#pragma unroll
    for (int ns = 0; ns < 4; ns++)
#pragma unroll
        for (int i = 0; i < 4; i++) acc[ns][i] = 0.f;

    // Layer 1: k = 128
#pragma unroll
    for (int kt = 0; kt < 8; kt++) {
        int ao = (m0 + g) * 136 + kt * 16 + t2;
        u32 ah0 = *(const u32*)(sAh + ao);
        u32 ah1 = *(const u32*)(sAh + ao + 8 * 136);
        u32 ah2 = *(const u32*)(sAh + ao + 8);
        u32 ah3 = *(const u32*)(sAh + ao + 8 * 136 + 8);
        u32 al0 = *(const u32*)(sAl + ao);
        u32 al1 = *(const u32*)(sAl + ao + 8 * 136);
        u32 al2 = *(const u32*)(sAl + ao + 8);
        u32 al3 = *(const u32*)(sAl + ao + 8 * 136 + 8);
#pragma unroll
        for (int ns = 0; ns < 4; ns++) {
            uint4 bv = __ldg(&g_w1f[(kt * 8 + ntb + ns) * 32 + lane]);
            mma3(acc[ns], ah0, ah1, ah2, ah3, al0, al1, al2, al3, bv);
        }
    }
    __syncthreads();
#pragma unroll
    for (int ns = 0; ns < 4; ns++) {
        int j0 = n0 + ns * 8 + t2;
        float b0 = sB1[j0], b1v = sB1[j0 + 1];
        int o1 = (m0 + g) * 72 + j0, o2 = (m0 + g + 8) * 72 + j0;
        st2split(sTh + o1, sTl + o1, fmaxf(acc[ns][0] + b0, 0.f), fmaxf(acc[ns][1] + b1v, 0.f));
        st2split(sTh + o2, sTl + o2, fmaxf(acc[ns][2] + b0, 0.f), fmaxf(acc[ns][3] + b1v, 0.f));
        acc[ns][0] = acc[ns][1] = acc[ns][2] = acc[ns][3] = 0.f;
    }
    __syncthreads();

    // Layer 2: k = 64
#pragma unroll
    for (int kt = 0; kt < 4; kt++) {
        int ao = (m0 + g) * 72 + kt * 16 + t2;
        u32 ah0 = *(const u32*)(sTh + ao);
        u32 ah1 = *(const u32*)(sTh + ao + 8 * 72);
        u32 ah2 = *(const u32*)(sTh + ao + 8);
        u32 ah3 = *(const u32*)(sTh + ao + 8 * 72 + 8);
        u32 al0 = *(const u32*)(sTl + ao);
        u32 al1 = *(const u32*)(sTl + ao + 8 * 72);
        u32 al2 = *(const u32*)(sTl + ao + 8);
        u32 al3 = *(const u32*)(sTl + ao + 8 * 72 + 8);
#pragma unroll
        for (int ns = 0; ns < 4; ns++) {
            uint4 bv = __ldg(&g_w2f[(kt * 8 + ntb + ns) * 32 + lane]);
            mma3(acc[ns], ah0, ah1, ah2, ah3, al0, al1, al2, al3, bv);
        }
    }
    {
        int n1 = base + m0 + g, n2 = n1 + 8;
#pragma unroll
        for (int ns = 0; ns < 4; ns++) {
            int j0 = n0 + ns * 8 + t2;
            float b0 = sB2[j0], b1v = sB2[j0 + 1];
            if (n1 < NN) {
                float v0 = fmaxf(acc[ns][0] + b0, 0.f), v1 = fmaxf(acc[ns][1] + b1v, 0.f);
                *(float2*)(g_h + (size_t)n1 * 64 + j0) = make_float2(v0, v1);
            }
            if (n2 < NN) {
                float v0 = fmaxf(acc[ns][2] + b0, 0.f), v1 = fmaxf(acc[ns][3] + b1v, 0.f);
                *(float2*)(g_h + (size_t)n2 * 64 + j0) = make_float2(v0, v1);
            }
        }
    }
}

// ---------------------------------------------------------------------------
// CSR gather-sum passes. Uniform trip count + esrc prefetch pipeline.
__global__ void agg1_kernel() {
    int warp = (blockIdx.x * 256 + threadIdx.x) >> 5;
    int lane = threadIdx.x & 31;
    int sub = lane >> 3;
    int c = lane & 7;
    int n = warp * 4 + sub;
    bool valid = n < NN;
    int beg = valid ? g_off[n] : 0;
    int end = valid ? g_off[n + 1] : 0;
    int nch = (__reduce_max_sync(0xffffffffu, end - beg) + 7) >> 3;
    float acc[8];
#pragma unroll
    for (int i = 0; i < 8; i++) acc[i] = 0.f;
    const uint4* hsrc = (const uint4*)g_hs;

    int idx = beg + c;
    int s = (idx < end) ? g_esrc[idx] : -1;
    for (int ch = 0; ch < nch; ch++) {
        int idxn = beg + (ch + 1) * 8 + c;
        int sn = (ch + 1 < nch && idxn < end) ? g_esrc[idxn] : -1;
#pragma unroll
        for (int jj = 0; jj < 8; jj++) {
            int sj = __shfl_sync(0xffffffffu, s, (lane & 24) + jj);
            if (sj >= 0) {
                uint4 u = hsrc[sj * 8 + c];
                float2 f0 = __half22float2(*(__half2*)&u.x);
                float2 f1 = __half22float2(*(__half2*)&u.y);
                float2 f2 = __half22float2(*(__half2*)&u.z);
                float2 f3 = __half22float2(*(__half2*)&u.w);
                acc[0] += f0.x; acc[1] += f0.y; acc[2] += f1.x; acc[3] += f1.y;
                acc[4] += f2.x; acc[5] += f2.y; acc[6] += f3.x; acc[7] += f3.y;
            }
        }
        s = sn;
    }
    if (valid) {
        ((float4*)g_agg)[n * 16 + c * 2]     = make_float4(acc[0], acc[1], acc[2], acc[3]);
        ((float4*)g_agg)[n * 16 + c * 2 + 1] = make_float4(acc[4], acc[5], acc[6], acc[7]);
        float di = dinv_of(n);
        float s2 = di * di;
        __half2 h0 = __floats2half2_rn(acc[0] * s2, acc[1] * s2);
        __half2 h1 = __floats2half2_rn(acc[2] * s2, acc[3] * s2);
        __half2 h2 = __floats2half2_rn(acc[4] * s2, acc[5] * s2);
        __half2 h3 = __floats2half2_rn(acc[6] * s2, acc[7] * s2);
        uint4 u;
        u.x = *(u32*)&h0; u.y = *(u32*)&h1; u.z = *(u32*)&h2; u.w = *(u32*)&h3;
        ((uint4*)g_aggs)[n * 8 + c] = u;
    }
}

__global__ void agg2_kernel() {
    int warp = (blockIdx.x * 256 + threadIdx.x) >> 5;
    int lane = threadIdx.x & 31;
    int sub = lane >> 3;
    int c = lane & 7;
    int n = warp * 4 + sub;
    bool valid = n < NN;
    int beg = valid ? g_off[n] : 0;
    int end = valid ? g_off[n + 1] : 0;
    int nch = (__reduce_max_sync(0xffffffffu, end - beg) + 7) >> 3;
    float acc[8];
#pragma unroll
    for (int i = 0; i < 8; i++) acc[i] = 0.f;
    const uint4* hsrc = (const uint4*)g_aggs;

    int idx = beg + c;
    int s = (idx < end) ? g_esrc[idx] : -1;
    for (int ch = 0; ch < nch; ch++) {
        int idxn = beg + (ch + 1) * 8 + c;
        int sn = (ch + 1 < nch && idxn < end) ? g_esrc[idxn] : -1;
#pragma unroll
        for (int jj = 0; jj < 8; jj++) {
            int sj = __shfl_sync(0xffffffffu, s, (lane & 24) + jj);
            if (sj >= 0) {
                uint4 u = hsrc[sj * 8 + c];
                float2 f0 = __half22float2(*(__half2*)&u.x);
                float2 f1 = __half22float2(*(__half2*)&u.y);
                float2 f2 = __half22float2(*(__half2*)&u.z);
                float2 f3 = __half22float2(*(__half2*)&u.w);
                acc[0] += f0.x; acc[1] += f0.y; acc[2] += f1.x; acc[3] += f1.y;
                acc[4] += f2.x; acc[5] += f2.y; acc[6] += f3.x; acc[7] += f3.y;
            }
        }
        s = sn;
    }
    if (valid) {
        ((float4*)g_B)[n * 16 + c * 2]     = make_float4(acc[0], acc[1], acc[2], acc[3]);
        ((float4*)g_B)[n * 16 + c * 2 + 1] = make_float4(acc[4], acc[5], acc[6], acc[7]);
    }
}

// ---------------------------------------------------------------------------
// Fused epilogue: poly-convs + single k=256 GEMM [hf(192) | hs(64)]·[W3 | M]^T.
#define F_HFH  0                 // half [64][200]  25600
#define F_HFL  25600
#define F_HSH  51200             // half [64][72]    9216
#define F_HSL  60416
#define F_EMB  51200             // float [64][68]  17408 (aliases HSH/HSL after GEMM)
#define F_LD   69632
#define F_CB   71936
#define F_B3   72704
#define F_W4   72960
#define F_B4   73472
#define FIN_SMEM_BYTES 73480

__global__ __launch_bounds__(256) void final_kernel(
    const float* __restrict__ cb1, const float* __restrict__ cb2,
    const float* __restrict__ cb3,
    const float* __restrict__ ld1, const float* __restrict__ ld2,
    const float* __restrict__ ld3,
    const float* __restrict__ b3,
    const float* __restrict__ W4, const float* __restrict__ b4,
    float* __restrict__ out_logits, float* __restrict__ out_emb)
{
    extern __shared__ char smc[];
    __half* s_hfh = (__half*)(smc + F_HFH);
    __half* s_hfl = (__half*)(smc + F_HFL);
    __half* s_hsh = (__half*)(smc + F_HSH);
    __half* s_hsl = (__half*)(smc + F_HSL);
    float*  s_emb = (float*)(smc + F_EMB);
    float*  s_ld  = (float*)(smc + F_LD);
    float*  s_cb  = (float*)(smc + F_CB);
    float*  s_b3  = (float*)(smc + F_B3);
    float*  s_w4  = (float*)(smc + F_W4);
    float*  s_b4  = (float*)(smc + F_B4);

    int tid = threadIdx.x;
    int base = blockIdx.x * 64;

    if (tid < 64) {
        int j = tid;
#pragma unroll
        for (int r = 0; r < 3; r++) {
            s_ld[(0 + r) * 64 + j] = ld1[r * 64 + j];
            s_ld[(3 + r) * 64 + j] = ld2[r * 64 + j];
            s_ld[(6 + r) * 64 + j] = ld3[r * 64 + j];
        }
        s_cb[j] = cb1[j]; s_cb[64 + j] = cb2[j]; s_cb[128 + j] = cb3[j];
        s_b3[j] = b3[j];
        s_w4[j] = W4[j]; s_w4[64 + j] = W4[64 + j];
    }
    if (tid < 2) s_b4[tid] = b4[tid];
    __syncthreads();

    // Phase 1: elementwise poly-conv parts -> s_hf (hi/lo), s_hs (hi/lo)
    {
        int j2 = (tid & 31) * 2, gg = tid >> 5;
#pragma unroll
        for (int it = 0; it < 8; it++) {
            int rowl = it * 8 + gg;
            int n = base + rowl;
            float di = (n < NN) ? dinv_of(n) : 1.f;
            float hv[2], a[2], Bv[2];
#pragma unroll
            for (int u = 0; u < 2; u++) {
                int j = j2 + u;
                hv[u] = 0.f; a[u] = 0.f; Bv[u] = 0.f;
                if (n < NN) {
                    hv[u] = g_h[(size_t)n * 64 + j];
                    a[u]  = g_agg[(size_t)n * 64 + j];
                    Bv[u] = g_B[(size_t)n * 64 + j];
                }
            }
            float o0[2], o1[2], o2[2], os[2];
#pragma unroll
            for (int u = 0; u < 2; u++) {
                int j = j2 + u;
                float gv = a[u] * di;
                float l1 = s_ld[1 * 64 + j], l2 = s_ld[2 * 64 + j];
                float f1 = hv[u] - l1 * gv;
                float f2 = f1 - l2 * ((a[u] - l1 * Bv[u]) * di);
                o0[u] = s_cb[j] - 3.f * f1 + 0.75f * f2;
                l1 = s_ld[4 * 64 + j]; l2 = s_ld[5 * 64 + j];
                f1 = hv[u] - l1 * gv;
                f2 = f1 - l2 * ((a[u] - l1 * Bv[u]) * di);
                o1[u] = s_cb[64 + j] + 3.f * f1 - 1.5f * f2;
                l1 = s_ld[7 * 64 + j]; l2 = s_ld[8 * 64 + j];
                f1 = hv[u] - l1 * gv;
                f2 = f1 - l2 * ((a[u] - l1 * Bv[u]) * di);
                o2[u] = s_cb[128 + j] + 0.75f * f2;
                os[u] = hv[u] * s_ld[0 * 64 + j];
            }
            st2split(s_hfh + rowl * 200 + j2,       s_hfl + rowl * 200 + j2,       o0[0], o0[1]);
            st2split(s_hfh + rowl * 200 + 64 + j2,  s_hfl + rowl * 200 + 64 + j2,  o1[0], o1[1]);
            st2split(s_hfh + rowl * 200 + 128 + j2, s_hfl + rowl * 200 + 128 + j2, o2[0], o2[1]);
            st2split(s_hsh + rowl * 72 + j2,        s_hsl + rowl * 72 + j2,        os[0], os[1]);
        }
    }
    __syncthreads();

    int wid = tid >> 5, lane = tid & 31;
    int g = lane >> 2, t2 = (lane & 3) * 2;
    int m0 = (wid & 3) * 16, n0 = (wid >> 2) * 32;
    int ntb = (wid >> 2) * 4;

    float acc[4][4];
#pragma unroll
    for (int ns = 0; ns < 4; ns++)
#pragma unroll
        for (int i = 0; i < 4; i++) acc[ns][i] = 0.f;

    // Single GEMM: emb = relu([hf | h*ld1_0] @ [W3 | M]^T + b3)   (k = 256)
#pragma unroll
    for (int kt = 0; kt < 16; kt++) {
        const __half *pah, *pal;
        int ao;
        if (kt < 12) { ao = (m0 + g) * 200 + kt * 16 + t2;        pah = s_hfh; pal = s_hfl; }
        else         { ao = (m0 + g) * 72 + (kt - 12) * 16 + t2;  pah = s_hsh; pal = s_hsl; }
        int rs = (kt < 12) ? 200 : 72;
        u32 ah0 = *(const u32*)(pah + ao);
        u32 ah1 = *(const u32*)(pah + ao + 8 * rs);
        u32 ah2 = *(const u32*)(pah + ao + 8);
        u32 ah3 = *(const u32*)(pah + ao + 8 * rs + 8);
        u32 al0 = *(const u32*)(pal + ao);
        u32 al1 = *(const u32*)(pal + ao + 8 * rs);
        u32 al2 = *(const u32*)(pal + ao + 8);
        u32 al3 = *(const u32*)(pal + ao + 8 * rs + 8);
#pragma unroll
        for (int ns = 0; ns < 4; ns++) {
            uint4 bv = (kt < 12)
                ? __ldg(&g_w3f[(kt * 8 + ntb + ns) * 32 + lane])
                : __ldg(&g_mf[((kt - 12) * 8 + ntb + ns) * 32 + lane]);
            mma3(acc[ns], ah0, ah1, ah2, ah3, al0, al1, al2, al3, bv);
        }
    }
    __syncthreads();   // hs reads done; s_emb alias safe
    {
        int n1 = base + m0 + g, n2 = n1 + 8;
#pragma unroll
        for (int ns = 0; ns < 4; ns++) {
            int j0 = n0 + ns * 8 + t2;
            float b0 = s_b3[j0], b1v = s_b3[j0 + 1];
            float v0 = fmaxf(acc[ns][0] + b0, 0.f), v1 = fmaxf(acc[ns][1] + b1v, 0.f);
            float v2 = fmaxf(acc[ns][2] + b0, 0.f), v3 = fmaxf(acc[ns][3] + b1v, 0.f);
            s_emb[(m0 + g) * 68 + j0]     = v0;
            s_emb[(m0 + g) * 68 + j0 + 1] = v1;
            s_emb[(m0 + g + 8) * 68 + j0]     = v2;
            s_emb[(m0 + g + 8) * 68 + j0 + 1] = v3;
            if (n1 < NN) *(float2*)(out_emb + (size_t)n1 * 64 + j0) = make_float2(v0, v1);
            if (n2 < NN) *(float2*)(out_emb + (size_t)n2 * 64 + j0) = make_float2(v2, v3);
        }
    }
    __syncthreads();

    // logits = emb @ W4^T + b4
    if (tid < 128) {
        int rowl = tid >> 1, c = tid & 1;
        int n = base + rowl;
        if (n < NN) {
            float a2 = s_b4[c];
            const float* er = s_emb + rowl * 68;
            const float* wr = s_w4 + c * 64;
#pragma unroll 8
            for (int k = 0; k < 64; k++) a2 += wr[k] * er[k];
            out_logits[n * 2 + c] = a2;
        }
    }
}

// ---------------------------------------------------------------------------
extern "C" void kernel_launch(void* const* d_in, const int* in_sizes, int n_in,
                              void* d_out, int out_size) {
    const float* in_feat = (const float*)d_in[0];
    const int*   src     = (const int*)d_in[1];
    const int*   dst     = (const int*)d_in[2];
    const float* W1  = (const float*)d_in[3];
    const float* b1  = (const float*)d_in[4];
    const float* W2  = (const float*)d_in[5];
    const float* b2  = (const float*)d_in[6];
    const float* W3  = (const float*)d_in[7];
    const float* b3  = (const float*)d_in[8];
    const float* W4  = (const float*)d_in[9];
    const float* b4  = (const float*)d_in[10];
    const float* ld1 = (const float*)d_in[11];
    const float* cW1 = (const float*)d_in[12];
    const float* cb1 = (const float*)d_in[13];
    const float* ld2 = (const float*)d_in[14];
    const float* cb2 = (const float*)d_in[16];
    const float* ld3 = (const float*)d_in[17];
    const float* cb3 = (const float*)d_in[19];

    float* out_logits = (float*)d_out;             // (N, 2)
    float* out_emb    = (float*)d_out + 2 * NN;    // (N, 64)

    static cudaStream_t s_mlp = 0, s_aux = 0;
    static cudaEvent_t  ev_fork = 0, ev_degi = 0, ev_join = 0, ev_mf = 0;
    if (!s_mlp) {
        cudaStreamCreateWithFlags(&s_mlp, cudaStreamNonBlocking);
        cudaStreamCreateWithFlags(&s_aux, cudaStreamNonBlocking);
        cudaEventCreateWithFlags(&ev_fork, cudaEventDisableTiming);
        cudaEventCreateWithFlags(&ev_degi, cudaEventDisableTiming);
        cudaEventCreateWithFlags(&ev_join, cudaEventDisableTiming);
        cudaEventCreateWithFlags(&ev_mf, cudaEventDisableTiming);
        cudaFuncSetAttribute(mlp_kernel, cudaFuncAttributeMaxDynamicSharedMemorySize, MLP_SMEM_BYTES);
        cudaFuncSetAttribute(final_kernel, cudaFuncAttributeMaxDynamicSharedMemorySize, FIN_SMEM_BYTES);
    }

    const int nblk = (NN + 63) / 64;   // 1563
    const int eblk = EE / 256;         // 6250

    // Head (stream 0): prep (weights + degree zeroing)
    prep_kernel<<<NB, 256>>>(W1, W2, cW1, W3);

    // Fork: MLP (stream B) and M-fusion (stream aux) run off-critical-path
    cudaEventRecord(ev_fork, 0);
    cudaStreamWaitEvent(s_mlp, ev_fork, 0);
    mlp_kernel<<<nblk, 256, MLP_SMEM_BYTES, s_mlp>>>(in_feat, b1, b2);
    cudaStreamWaitEvent(s_aux, ev_fork, 0);
    mfuse_kernel<<<1, 256, 0, s_aux>>>(cW1, W3);
    cudaEventRecord(ev_mf, s_aux);

    // Stream 0: degrees + ranks, then CSR build
    degi_kernel<<<eblk, 256>>>(dst);
    cudaEventRecord(ev_degi, 0);
    scan1_kernel<<<NB, 256>>>();
    scan23_kernel<<<NB, 256>>>();
    csr_fill_kernel<<<eblk, 256>>>(src, dst);

    // Stream B: hs = fp16(h * dinv) once both mlp (h) and degi (deg) are done
    cudaStreamWaitEvent(s_mlp, ev_degi, 0);
    scale_kernel<<<(NN * 32 + 255) / 256, 256, 0, s_mlp>>>();
    cudaEventRecord(ev_join, s_mlp);

    // Join: aggregation needs hs (stream B) and the CSR (stream 0)
    cudaStreamWaitEvent(0, ev_join, 0);
    agg1_kernel<<<(NN / 4 + 7) / 8, 256>>>();
    agg2_kernel<<<(NN / 4 + 7) / 8, 256>>>();
    cudaStreamWaitEvent(0, ev_mf, 0);
    final_kernel<<<nblk, 256, FIN_SMEM_BYTES>>>(cb1, cb2, cb3, ld1, ld2, ld3,
                                                b3, W4, b4, out_logits, out_emb);
}

// round 15
// speedup vs baseline: 1.2220x; 1.2220x over previous
#include <cuda_runtime.h>
#include <cuda_fp16.h>

#define NN 100000
#define EE 1600000
#define HD 64
#define NB 391            // ceil(NN/256)

typedef unsigned long long ull;
typedef unsigned int u32;

// Scratch (device globals: no allocation allowed)
__device__ int    g_degi[NN];
__device__ int    g_off[NN + 1];
__device__ int    g_part[NB];
__device__ int    g_rank[EE];       // edge's arrival rank within its dst
__device__ int    g_esrc[EE];
__device__ float  g_h[NN * HD];
__device__ __half g_hs[NN * HD];    // h * dinv   (fp16: non-negative summands)
__device__ float  g_agg[NN * HD];   // segsum(hs)
__device__ __half g_aggs[NN * HD];  // agg * dinv^2 (fp16)
__device__ float  g_B[NN * HD];     // segsum(aggs)

// Pre-split weight fragments: uint4{bh0,bh1,bl0,bl1} per (kt, ntile, lane)
__device__ uint4  g_w1f[8 * 8 * 32];    // W1  [64][128]: 8 kt x 8 nt
__device__ uint4  g_w2f[4 * 8 * 32];    // W2  [64][64]:  4 kt x 8 nt
__device__ uint4  g_cw1f[4 * 8 * 32];   // cW1 [64][64]
__device__ uint4  g_w3f[12 * 8 * 32];   // W3  [64][192]: 12 kt x 8 nt

// ---------------------------------------------------------------------------
__device__ __forceinline__ void mma16816(float* c, u32 a0, u32 a1, u32 a2, u32 a3,
                                         u32 b0, u32 b1) {
    asm volatile(
        "mma.sync.aligned.m16n8k16.row.col.f32.f16.f16.f32 "
        "{%0,%1,%2,%3}, {%4,%5,%6,%7}, {%8,%9}, {%0,%1,%2,%3};"
        : "+f"(c[0]), "+f"(c[1]), "+f"(c[2]), "+f"(c[3])
        : "r"(a0), "r"(a1), "r"(a2), "r"(a3), "r"(b0), "r"(b1));
}

// 3-term split-fp16 MMA: C += Ah*Bh + Al*Bh + Ah*Bl
__device__ __forceinline__ void mma3(float* c,
                                     u32 ah0, u32 ah1, u32 ah2, u32 ah3,
                                     u32 al0, u32 al1, u32 al2, u32 al3,
                                     uint4 b) {
    mma16816(c, ah0, ah1, ah2, ah3, b.x, b.y);
    mma16816(c, al0, al1, al2, al3, b.x, b.y);
    mma16816(c, ah0, ah1, ah2, ah3, b.z, b.w);
}

__device__ __forceinline__ void st4split(__half* ph, __half* pl, float4 v) {
    __half2 h0 = __floats2half2_rn(v.x, v.y);
    float2 f0 = __half22float2(h0);
    __half2 l0 = __floats2half2_rn(v.x - f0.x, v.y - f0.y);
    __half2 h1 = __floats2half2_rn(v.z, v.w);
    float2 f1 = __half22float2(h1);
    __half2 l1 = __floats2half2_rn(v.z - f1.x, v.w - f1.y);
    *(__half2*)ph = h0; *(__half2*)(ph + 2) = h1;
    *(__half2*)pl = l0; *(__half2*)(pl + 2) = l1;
}

__device__ __forceinline__ void st2split(__half* ph, __half* pl, float x, float y) {
    __half2 h = __floats2half2_rn(x, y);
    float2 f = __half22float2(h);
    *(__half2*)ph = h;
    *(__half2*)pl = __floats2half2_rn(x - f.x, y - f.y);
}

__device__ __forceinline__ float dinv_of(int n) {
    return rsqrtf(fmaxf((float)g_degi[n], 1.0f));
}

// ---------------------------------------------------------------------------
__global__ void zero_deg_kernel() {
    int i = blockIdx.x * 256 + threadIdx.x;
    if (i < NN) g_degi[i] = 0;
}

// Weight pre-split into fragment order (28 blocks, off critical path)
__global__ void wsplit_kernel(const float* __restrict__ W1, const float* __restrict__ W2,
                              const float* __restrict__ cW1, const float* __restrict__ W3) {
    int i = blockIdx.x * 256 + threadIdx.x;
    if (i >= 224 * 32) return;
    int gfrag = i >> 5, lane = i & 31;
    const float* W; uint4* out; int K; int g;
    if (gfrag < 64)       { W = W1;  out = g_w1f;  K = 128; g = gfrag; }
    else if (gfrag < 96)  { W = W2;  out = g_w2f;  K = 64;  g = gfrag - 64; }
    else if (gfrag < 128) { W = cW1; out = g_cw1f; K = 64;  g = gfrag - 96; }
    else                  { W = W3;  out = g_w3f;  K = 192; g = gfrag - 128; }
    int kt = g >> 3, nt = g & 7;
    int n = nt * 8 + (lane >> 2), k = kt * 16 + (lane & 3) * 2;
    const float* p = W + n * K + k;
    float w0 = p[0], w1 = p[1], w8 = p[8], w9 = p[9];
    __half2 h0 = __floats2half2_rn(w0, w1);
    float2 f0 = __half22float2(h0);
    __half2 l0 = __floats2half2_rn(w0 - f0.x, w1 - f0.y);
    __half2 h1 = __floats2half2_rn(w8, w9);
    float2 f1 = __half22float2(h1);
    __half2 l1 = __floats2half2_rn(w8 - f1.x, w9 - f1.y);
    uint4 v;
    v.x = *(u32*)&h0; v.y = *(u32*)&h1; v.z = *(u32*)&l0; v.w = *(u32*)&l1;
    out[g * 32 + lane] = v;
}

// ---------------------------------------------------------------------------
// Degrees + per-edge arrival rank; 4 edges/thread (int4) for atomic MLP.
__global__ void degi_kernel(const int* __restrict__ dst) {
    int i = blockIdx.x * 256 + threadIdx.x;   // int4 index
    if (i < EE / 4) {
        int4 d = ((const int4*)dst)[i];
        int4 r;
        r.x = atomicAdd(&g_degi[d.x], 1);
        r.y = atomicAdd(&g_degi[d.y], 1);
        r.z = atomicAdd(&g_degi[d.z], 1);
        r.w = atomicAdd(&g_degi[d.w], 1);
        ((int4*)g_rank)[i] = r;
    }
}

__global__ void scan1_kernel() {
    __shared__ int s[256];
    int t = threadIdx.x;
    int i = blockIdx.x * 256 + t;
    int v = (i < NN) ? g_degi[i] : 0;
    s[t] = v;
    __syncthreads();
#pragma unroll
    for (int d = 1; d < 256; d <<= 1) {
        int tv = (t >= d) ? s[t - d] : 0;
        __syncthreads();
        s[t] += tv;
        __syncthreads();
    }
    if (i < NN) g_off[i] = s[t] - v;
    if (t == 255) g_part[blockIdx.x] = s[255];
}

__global__ void scan23_kernel() {
    __shared__ int ssum[256];
    int t = threadIdx.x, bid = blockIdx.x;
    int v = 0;
    for (int i = t; i < bid; i += 256) v += g_part[i];
    ssum[t] = v;
    __syncthreads();
#pragma unroll
    for (int d = 128; d > 0; d >>= 1) {
        if (t < d) ssum[t] += ssum[t + d];
        __syncthreads();
    }
    int prefix = ssum[0];
    int i = bid * 256 + t;
    if (i < NN) g_off[i] += prefix;
    if (i == 0) g_off[NN] = EE;
}

// Atomic-free CSR fill using precomputed ranks; 4 edges/thread.
__global__ void csr_fill_kernel(const int* __restrict__ src, const int* __restrict__ dst) {
    int i = blockIdx.x * 256 + threadIdx.x;
    if (i < EE / 4) {
        int4 d = ((const int4*)dst)[i];
        int4 r = ((const int4*)g_rank)[i];
        int4 s = ((const int4*)src)[i];
        g_esrc[g_off[d.x] + r.x] = s.x;
        g_esrc[g_off[d.y] + r.y] = s.y;
        g_esrc[g_off[d.z] + r.z] = s.z;
        g_esrc[g_off[d.w] + r.w] = s.w;
    }
}

// Coalesced hs = fp16(h * dinv).
__global__ void scale_kernel() {
    int i = blockIdx.x * 256 + threadIdx.x;
    if (i < NN * 32) {
        int n = i >> 5;
        float di = dinv_of(n);
        float2 h = ((const float2*)g_h)[i];
        ((__half2*)g_hs)[i] = __floats2half2_rn(h.x * di, h.y * di);
    }
}

// ---------------------------------------------------------------------------
// Fused 2-layer MLP, split-fp16 tensor cores; weights from pre-split frags.
#define M_AH   0                 // half [64][136]  17408
#define M_AL   17408
#define M_TH   0                 // aliases AH after L1
#define M_TL   9216
#define M_B1   34816
#define M_B2   35072
#define MLP_SMEM_BYTES 35328

__global__ __launch_bounds__(256) void mlp_kernel(
    const float* __restrict__ X, const float* __restrict__ b1,
    const float* __restrict__ b2)
{
    extern __shared__ char smc[];
    __half* sAh = (__half*)(smc + M_AH);
    __half* sAl = (__half*)(smc + M_AL);
    __half* sTh = (__half*)(smc + M_TH);
    __half* sTl = (__half*)(smc + M_TL);
    float*  sB1 = (float*)(smc + M_B1);
    float*  sB2 = (float*)(smc + M_B2);

    int tid = threadIdx.x;
    int base = blockIdx.x * 64;

    for (int i = tid; i < 2048; i += 256) {
        int row = i >> 5, q = i & 31;
        float4 v = make_float4(0.f, 0.f, 0.f, 0.f);
        if (base + row < NN) v = *(const float4*)(X + (size_t)(base + row) * 128 + q * 4);
        st4split(sAh + row * 136 + q * 4, sAl + row * 136 + q * 4, v);
    }
    if (tid < 64) { sB1[tid] = b1[tid]; sB2[tid] = b2[tid]; }
    __syncthreads();

    int wid = tid >> 5, lane = tid & 31;
    int g = lane >> 2, t2 = (lane & 3) * 2;
    int m0 = (wid & 3) * 16, n0 = (wid >> 2) * 32;
    int ntb = (wid >> 2) * 4;

    float acc[4][4];
#pragma unroll
    for (int ns = 0; ns < 4; ns++)
#pragma unroll
        for (int i = 0; i < 4; i++) acc[ns][i] = 0.f;

    // Layer 1: k = 128
#pragma unroll
    for (int kt = 0; kt < 8; kt++) {
        int ao = (m0 + g) * 136 + kt * 16 + t2;
        u32 ah0 = *(const u32*)(sAh + ao);
        u32 ah1 = *(const u32*)(sAh + ao + 8 * 136);
        u32 ah2 = *(const u32*)(sAh + ao + 8);
        u32 ah3 = *(const u32*)(sAh + ao + 8 * 136 + 8);
        u32 al0 = *(const u32*)(sAl + ao);
        u32 al1 = *(const u32*)(sAl + ao + 8 * 136);
        u32 al2 = *(const u32*)(sAl + ao + 8);
        u32 al3 = *(const u32*)(sAl + ao + 8 * 136 + 8);
#pragma unroll
        for (int ns = 0; ns < 4; ns++) {
            uint4 bv = __ldg(&g_w1f[(kt * 8 + ntb + ns) * 32 + lane]);
            mma3(acc[ns], ah0, ah1, ah2, ah3, al0, al1, al2, al3, bv);
        }
    }
    __syncthreads();
#pragma unroll
    for (int ns = 0; ns < 4; ns++) {
        int j0 = n0 + ns * 8 + t2;
        float b0 = sB1[j0], b1v = sB1[j0 + 1];
        int o1 = (m0 + g) * 72 + j0, o2 = (m0 + g + 8) * 72 + j0;
        st2split(sTh + o1, sTl + o1, fmaxf(acc[ns][0] + b0, 0.f), fmaxf(acc[ns][1] + b1v, 0.f));
        st2split(sTh + o2, sTl + o2, fmaxf(acc[ns][2] + b0, 0.f), fmaxf(acc[ns][3] + b1v, 0.f));
        acc[ns][0] = acc[ns][1] = acc[ns][2] = acc[ns][3] = 0.f;
    }
    __syncthreads();

    // Layer 2: k = 64
#pragma unroll
    for (int kt = 0; kt < 4; kt++) {
        int ao = (m0 + g) * 72 + kt * 16 + t2;
        u32 ah0 = *(const u32*)(sTh + ao);
        u32 ah1 = *(const u32*)(sTh + ao + 8 * 72);
        u32 ah2 = *(const u32*)(sTh + ao + 8);
        u32 ah3 = *(const u32*)(sTh + ao + 8 * 72 + 8);
        u32 al0 = *(const u32*)(sTl + ao);
        u32 al1 = *(const u32*)(sTl + ao + 8 * 72);
        u32 al2 = *(const u32*)(sTl + ao + 8);
        u32 al3 = *(const u32*)(sTl + ao + 8 * 72 + 8);
#pragma unroll
        for (int ns = 0; ns < 4; ns++) {
            uint4 bv = __ldg(&g_w2f[(kt * 8 + ntb + ns) * 32 + lane]);
            mma3(acc[ns], ah0, ah1, ah2, ah3, al0, al1, al2, al3, bv);
        }
    }
    {
        int n1 = base + m0 + g, n2 = n1 + 8;
#pragma unroll
        for (int ns = 0; ns < 4; ns++) {
            int j0 = n0 + ns * 8 + t2;
            float b0 = sB2[j0], b1v = sB2[j0 + 1];
            if (n1 < NN) {
                float v0 = fmaxf(acc[ns][0] + b0, 0.f), v1 = fmaxf(acc[ns][1] + b1v, 0.f);
                *(float2*)(g_h + (size_t)n1 * 64 + j0) = make_float2(v0, v1);
            }
            if (n2 < NN) {
                float v0 = fmaxf(acc[ns][2] + b0, 0.f), v1 = fmaxf(acc[ns][3] + b1v, 0.f);
                *(float2*)(g_h + (size_t)n2 * 64 + j0) = make_float2(v0, v1);
            }
        }
    }
}

// ---------------------------------------------------------------------------
// CSR gather-sum passes. Uniform trip count + esrc prefetch pipeline.
__global__ void agg1_kernel() {
    int warp = (blockIdx.x * 256 + threadIdx.x) >> 5;
    int lane = threadIdx.x & 31;
    int sub = lane >> 3;
    int c = lane & 7;
    int n = warp * 4 + sub;
    bool valid = n < NN;
    int beg = valid ? g_off[n] : 0;
    int end = valid ? g_off[n + 1] : 0;
    int nch = (__reduce_max_sync(0xffffffffu, end - beg) + 7) >> 3;
    float acc[8];
#pragma unroll
    for (int i = 0; i < 8; i++) acc[i] = 0.f;
    const uint4* hsrc = (const uint4*)g_hs;

    int idx = beg + c;
    int s = (idx < end) ? g_esrc[idx] : -1;
    for (int ch = 0; ch < nch; ch++) {
        int idxn = beg + (ch + 1) * 8 + c;
        int sn = (ch + 1 < nch && idxn < end) ? g_esrc[idxn] : -1;
#pragma unroll
        for (int jj = 0; jj < 8; jj++) {
            int sj = __shfl_sync(0xffffffffu, s, (lane & 24) + jj);
            if (sj >= 0) {
                uint4 u = hsrc[sj * 8 + c];
                float2 f0 = __half22float2(*(__half2*)&u.x);
                float2 f1 = __half22float2(*(__half2*)&u.y);
                float2 f2 = __half22float2(*(__half2*)&u.z);
                float2 f3 = __half22float2(*(__half2*)&u.w);
                acc[0] += f0.x; acc[1] += f0.y; acc[2] += f1.x; acc[3] += f1.y;
                acc[4] += f2.x; acc[5] += f2.y; acc[6] += f3.x; acc[7] += f3.y;
            }
        }
        s = sn;
    }
    if (valid) {
        ((float4*)g_agg)[n * 16 + c * 2]     = make_float4(acc[0], acc[1], acc[2], acc[3]);
        ((float4*)g_agg)[n * 16 + c * 2 + 1] = make_float4(acc[4], acc[5], acc[6], acc[7]);
        float di = dinv_of(n);
        float s2 = di * di;
        __half2 h0 = __floats2half2_rn(acc[0] * s2, acc[1] * s2);
        __half2 h1 = __floats2half2_rn(acc[2] * s2, acc[3] * s2);
        __half2 h2 = __floats2half2_rn(acc[4] * s2, acc[5] * s2);
        __half2 h3 = __floats2half2_rn(acc[6] * s2, acc[7] * s2);
        uint4 u;
        u.x = *(u32*)&h0; u.y = *(u32*)&h1; u.z = *(u32*)&h2; u.w = *(u32*)&h3;
        ((uint4*)g_aggs)[n * 8 + c] = u;
    }
}

__global__ void agg2_kernel() {
    int warp = (blockIdx.x * 256 + threadIdx.x) >> 5;
    int lane = threadIdx.x & 31;
    int sub = lane >> 3;
    int c = lane & 7;
    int n = warp * 4 + sub;
    bool valid = n < NN;
    int beg = valid ? g_off[n] : 0;
    int end = valid ? g_off[n + 1] : 0;
    int nch = (__reduce_max_sync(0xffffffffu, end - beg) + 7) >> 3;
    float acc[8];
#pragma unroll
    for (int i = 0; i < 8; i++) acc[i] = 0.f;
    const uint4* hsrc = (const uint4*)g_aggs;

    int idx = beg + c;
    int s = (idx < end) ? g_esrc[idx] : -1;
    for (int ch = 0; ch < nch; ch++) {
        int idxn = beg + (ch + 1) * 8 + c;
        int sn = (ch + 1 < nch && idxn < end) ? g_esrc[idxn] : -1;
#pragma unroll
        for (int jj = 0; jj < 8; jj++) {
            int sj = __shfl_sync(0xffffffffu, s, (lane & 24) + jj);
            if (sj >= 0) {
                uint4 u = hsrc[sj * 8 + c];
                float2 f0 = __half22float2(*(__half2*)&u.x);
                float2 f1 = __half22float2(*(__half2*)&u.y);
                float2 f2 = __half22float2(*(__half2*)&u.z);
                float2 f3 = __half22float2(*(__half2*)&u.w);
                acc[0] += f0.x; acc[1] += f0.y; acc[2] += f1.x; acc[3] += f1.y;
                acc[4] += f2.x; acc[5] += f2.y; acc[6] += f3.x; acc[7] += f3.y;
            }
        }
        s = sn;
    }
    if (valid) {
        ((float4*)g_B)[n * 16 + c * 2]     = make_float4(acc[0], acc[1], acc[2], acc[3]);
        ((float4*)g_B)[n * 16 + c * 2 + 1] = make_float4(acc[4], acc[5], acc[6], acc[7]);
    }
}

// ---------------------------------------------------------------------------
// Fused epilogue, split-fp16 tensor cores (R13 structure).
#define F_HFH  0                 // half [64][200]  25600
#define F_HFL  25600
#define F_HSH  51200             // half [64][72]    9216
#define F_HSL  60416
#define F_EMB  51200             // float [64][68]  17408 (aliases HSH/HSL after ph2)
#define F_LD   69632
#define F_CB   71936
#define F_B3   72704
#define F_W4   72960
#define F_B4   73472
#define FIN_SMEM_BYTES 73480

__global__ __launch_bounds__(256) void final_kernel(
    const float* __restrict__ cb1, const float* __restrict__ cb2,
    const float* __restrict__ cb3,
    const float* __restrict__ ld1, const float* __restrict__ ld2,
    const float* __restrict__ ld3,
    const float* __restrict__ b3,
    const float* __restrict__ W4, const float* __restrict__ b4,
    float* __restrict__ out_logits, float* __restrict__ out_emb)
{
    extern __shared__ char smc[];
    __half* s_hfh = (__half*)(smc + F_HFH);
    __half* s_hfl = (__half*)(smc + F_HFL);
    __half* s_hsh = (__half*)(smc + F_HSH);
    __half* s_hsl = (__half*)(smc + F_HSL);
    float*  s_emb = (float*)(smc + F_EMB);
    float*  s_ld  = (float*)(smc + F_LD);
    float*  s_cb  = (float*)(smc + F_CB);
    float*  s_b3  = (float*)(smc + F_B3);
    float*  s_w4  = (float*)(smc + F_W4);
    float*  s_b4  = (float*)(smc + F_B4);

    int tid = threadIdx.x;
    int base = blockIdx.x * 64;

    if (tid < 64) {
        int j = tid;
#pragma unroll
        for (int r = 0; r < 3; r++) {
            s_ld[(0 + r) * 64 + j] = ld1[r * 64 + j];
            s_ld[(3 + r) * 64 + j] = ld2[r * 64 + j];
            s_ld[(6 + r) * 64 + j] = ld3[r * 64 + j];
        }
        s_cb[j] = cb1[j]; s_cb[64 + j] = cb2[j]; s_cb[128 + j] = cb3[j];
        s_b3[j] = b3[j];
        s_w4[j] = W4[j]; s_w4[64 + j] = W4[64 + j];
    }
    if (tid < 2) s_b4[tid] = b4[tid];
    __syncthreads();

    // Phase 1: elementwise poly-conv parts -> s_hf (hi/lo), s_hs (hi/lo)
    {
        int j2 = (tid & 31) * 2, gg = tid >> 5;
#pragma unroll
        for (int it = 0; it < 8; it++) {
            int rowl = it * 8 + gg;
            int n = base + rowl;
            float di = (n < NN) ? dinv_of(n) : 1.f;
            float hv[2], a[2], Bv[2];
#pragma unroll
            for (int u = 0; u < 2; u++) {
                int j = j2 + u;
                hv[u] = 0.f; a[u] = 0.f; Bv[u] = 0.f;
                if (n < NN) {
                    hv[u] = g_h[(size_t)n * 64 + j];
                    a[u]  = g_agg[(size_t)n * 64 + j];
                    Bv[u] = g_B[(size_t)n * 64 + j];
                }
            }
            float o0[2], o1[2], o2[2], os[2];
#pragma unroll
            for (int u = 0; u < 2; u++) {
                int j = j2 + u;
                float gv = a[u] * di;
                float l1 = s_ld[1 * 64 + j], l2 = s_ld[2 * 64 + j];
                float f1 = hv[u] - l1 * gv;
                float f2 = f1 - l2 * ((a[u] - l1 * Bv[u]) * di);
                o0[u] = s_cb[j] - 3.f * f1 + 0.75f * f2;
                l1 = s_ld[4 * 64 + j]; l2 = s_ld[5 * 64 + j];
                f1 = hv[u] - l1 * gv;
                f2 = f1 - l2 * ((a[u] - l1 * Bv[u]) * di);
                o1[u] = s_cb[64 + j] + 3.f * f1 - 1.5f * f2;
                l1 = s_ld[7 * 64 + j]; l2 = s_ld[8 * 64 + j];
                f1 = hv[u] - l1 * gv;
                f2 = f1 - l2 * ((a[u] - l1 * Bv[u]) * di);
                o2[u] = s_cb[128 + j] + 0.75f * f2;
                os[u] = hv[u] * s_ld[0 * 64 + j];
            }
            st2split(s_hfh + rowl * 200 + j2,       s_hfl + rowl * 200 + j2,       o0[0], o0[1]);
            st2split(s_hfh + rowl * 200 + 64 + j2,  s_hfl + rowl * 200 + 64 + j2,  o1[0], o1[1]);
            st2split(s_hfh + rowl * 200 + 128 + j2, s_hfl + rowl * 200 + 128 + j2, o2[0], o2[1]);
            st2split(s_hsh + rowl * 72 + j2,        s_hsl + rowl * 72 + j2,        os[0], os[1]);
        }
    }
    __syncthreads();

    int wid = tid >> 5, lane = tid & 31;
    int g = lane >> 2, t2 = (lane & 3) * 2;
    int m0 = (wid & 3) * 16, n0 = (wid >> 2) * 32;
    int ntb = (wid >> 2) * 4;

    float acc[4][4];
#pragma unroll
    for (int ns = 0; ns < 4; ns++)
#pragma unroll
        for (int i = 0; i < 4; i++) acc[ns][i] = 0.f;

    // Phase 2: hf[:,0:64] += 3 * (h*ld1_0) @ cW1^T   (k = 64)
#pragma unroll
    for (int kt = 0; kt < 4; kt++) {
        int ao = (m0 + g) * 72 + kt * 16 + t2;
        u32 ah0 = *(const u32*)(s_hsh + ao);
        u32 ah1 = *(const u32*)(s_hsh + ao + 8 * 72);
        u32 ah2 = *(const u32*)(s_hsh + ao + 8);
        u32 ah3 = *(const u32*)(s_hsh + ao + 8 * 72 + 8);
        u32 al0 = *(const u32*)(s_hsl + ao);
        u32 al1 = *(const u32*)(s_hsl + ao + 8 * 72);
        u32 al2 = *(const u32*)(s_hsl + ao + 8);
        u32 al3 = *(const u32*)(s_hsl + ao + 8 * 72 + 8);
#pragma unroll
        for (int ns = 0; ns < 4; ns++) {
            uint4 bv = __ldg(&g_cw1f[(kt * 8 + ntb + ns) * 32 + lane]);
            mma3(acc[ns], ah0, ah1, ah2, ah3, al0, al1, al2, al3, bv);
        }
    }
#pragma unroll
    for (int ns = 0; ns < 4; ns++) {
        int j0 = n0 + ns * 8 + t2;
        int o1 = (m0 + g) * 200 + j0, o2 = (m0 + g + 8) * 200 + j0;
        float2 h1 = __half22float2(*(__half2*)(s_hfh + o1));
        float2 l1 = __half22float2(*(__half2*)(s_hfl + o1));
        st2split(s_hfh + o1, s_hfl + o1,
                 h1.x + l1.x + 3.f * acc[ns][0], h1.y + l1.y + 3.f * acc[ns][1]);
        float2 h2 = __half22float2(*(__half2*)(s_hfh + o2));
        float2 l2 = __half22float2(*(__half2*)(s_hfl + o2));
        st2split(s_hfh + o2, s_hfl + o2,
                 h2.x + l2.x + 3.f * acc[ns][2], h2.y + l2.y + 3.f * acc[ns][3]);
        acc[ns][0] = acc[ns][1] = acc[ns][2] = acc[ns][3] = 0.f;
    }
    __syncthreads();

    // Phase 3: emb = relu(hf @ W3^T + b3)   (k = 192)
#pragma unroll
    for (int kt = 0; kt < 12; kt++) {
        int ao = (m0 + g) * 200 + kt * 16 + t2;
        u32 ah0 = *(const u32*)(s_hfh + ao);
        u32 ah1 = *(const u32*)(s_hfh + ao + 8 * 200);
        u32 ah2 = *(const u32*)(s_hfh + ao + 8);
        u32 ah3 = *(const u32*)(s_hfh + ao + 8 * 200 + 8);
        u32 al0 = *(const u32*)(s_hfl + ao);
        u32 al1 = *(const u32*)(s_hfl + ao + 8 * 200);
        u32 al2 = *(const u32*)(s_hfl + ao + 8);
        u32 al3 = *(const u32*)(s_hfl + ao + 8 * 200 + 8);
#pragma unroll
        for (int ns = 0; ns < 4; ns++) {
            uint4 bv = __ldg(&g_w3f[(kt * 8 + ntb + ns) * 32 + lane]);
            mma3(acc[ns], ah0, ah1, ah2, ah3, al0, al1, al2, al3, bv);
        }
    }
    {
        int n1 = base + m0 + g, n2 = n1 + 8;
#pragma unroll
        for (int ns = 0; ns < 4; ns++) {
            int j0 = n0 + ns * 8 + t2;
            float b0 = s_b3[j0], b1v = s_b3[j0 + 1];
            float v0 = fmaxf(acc[ns][0] + b0, 0.f), v1 = fmaxf(acc[ns][1] + b1v, 0.f);
            float v2 = fmaxf(acc[ns][2] + b0, 0.f), v3 = fmaxf(acc[ns][3] + b1v, 0.f);
            s_emb[(m0 + g) * 68 + j0]     = v0;
            s_emb[(m0 + g) * 68 + j0 + 1] = v1;
            s_emb[(m0 + g + 8) * 68 + j0]     = v2;
            s_emb[(m0 + g + 8) * 68 + j0 + 1] = v3;
            if (n1 < NN) *(float2*)(out_emb + (size_t)n1 * 64 + j0) = make_float2(v0, v1);
            if (n2 < NN) *(float2*)(out_emb + (size_t)n2 * 64 + j0) = make_float2(v2, v3);
        }
    }
    __syncthreads();

    // Phase 4: logits = emb @ W4^T + b4
    if (tid < 128) {
        int rowl = tid >> 1, c = tid & 1;
        int n = base + rowl;
        if (n < NN) {
            float a2 = s_b4[c];
            const float* er = s_emb + rowl * 68;
            const float* wr = s_w4 + c * 64;
#pragma unroll 8
            for (int k = 0; k < 64; k++) a2 += wr[k] * er[k];
            out_logits[n * 2 + c] = a2;
        }
    }
}

// ---------------------------------------------------------------------------
extern "C" void kernel_launch(void* const* d_in, const int* in_sizes, int n_in,
                              void* d_out, int out_size) {
    const float* in_feat = (const float*)d_in[0];
    const int*   src     = (const int*)d_in[1];
    const int*   dst     = (const int*)d_in[2];
    const float* W1  = (const float*)d_in[3];
    const float* b1  = (const float*)d_in[4];
    const float* W2  = (const float*)d_in[5];
    const float* b2  = (const float*)d_in[6];
    const float* W3  = (const float*)d_in[7];
    const float* b3  = (const float*)d_in[8];
    const float* W4  = (const float*)d_in[9];
    const float* b4  = (const float*)d_in[10];
    const float* ld1 = (const float*)d_in[11];
    const float* cW1 = (const float*)d_in[12];
    const float* cb1 = (const float*)d_in[13];
    const float* ld2 = (const float*)d_in[14];
    const float* cb2 = (const float*)d_in[16];
    const float* ld3 = (const float*)d_in[17];
    const float* cb3 = (const float*)d_in[19];

    float* out_logits = (float*)d_out;             // (N, 2)
    float* out_emb    = (float*)d_out + 2 * NN;    // (N, 64)

    static cudaStream_t s_aux = 0;
    static cudaEvent_t  ev_degi = 0, ev_join = 0;
    if (!s_aux) {
        cudaStreamCreateWithFlags(&s_aux, cudaStreamNonBlocking);
        cudaEventCreateWithFlags(&ev_degi, cudaEventDisableTiming);
        cudaEventCreateWithFlags(&ev_join, cudaEventDisableTiming);
        cudaFuncSetAttribute(mlp_kernel, cudaFuncAttributeMaxDynamicSharedMemorySize, MLP_SMEM_BYTES);
        cudaFuncSetAttribute(final_kernel, cudaFuncAttributeMaxDynamicSharedMemorySize, FIN_SMEM_BYTES);
    }

    const int nblk = (NN + 63) / 64;   // 1563

    // Aux stream: weight split -> MLP (depends only on weights/inputs)
    wsplit_kernel<<<28, 256, 0, s_aux>>>(W1, W2, cW1, W3);
    mlp_kernel<<<nblk, 256, MLP_SMEM_BYTES, s_aux>>>(in_feat, b1, b2);

    // Stream 0: degree zero -> degrees+ranks -> CSR build
    zero_deg_kernel<<<NB, 256>>>();
    degi_kernel<<<(EE / 4 + 255) / 256, 256>>>(dst);
    cudaEventRecord(ev_degi, 0);
    scan1_kernel<<<NB, 256>>>();
    scan23_kernel<<<NB, 256>>>();
    csr_fill_kernel<<<(EE / 4 + 255) / 256, 256>>>(src, dst);

    // Aux stream: hs = fp16(h * dinv) after mlp (program order) + degi (event)
    cudaStreamWaitEvent(s_aux, ev_degi, 0);
    scale_kernel<<<(NN * 32 + 255) / 256, 256, 0, s_aux>>>();
    cudaEventRecord(ev_join, s_aux);

    // Join: aggregation needs hs (aux) and the CSR (stream 0)
    cudaStreamWaitEvent(0, ev_join, 0);
    agg1_kernel<<<(NN / 4 + 7) / 8, 256>>>();
    agg2_kernel<<<(NN / 4 + 7) / 8, 256>>>();
    final_kernel<<<nblk, 256, FIN_SMEM_BYTES>>>(cb1, cb2, cb3, ld1, ld2, ld3,
                                                b3, W4, b4, out_logits, out_emb);
}